// round 7
// baseline (speedup 1.0000x reference)
#include <cuda_runtime.h>

// ---------------------------------------------------------------------------
// FullGraphModel — analytic form (final).
//
// Derivation (round 2, hardware-confirmed rel_err == 0.0 in rounds 1,2,3,5,6):
// the reference standardizes the nonzero decision-neuron values by THEIR OWN
// mean, so sum_nonzero((v - mean_nz)/std) == 0 identically; zero entries
// contribute 0. Hence pooled == 0 exactly and
//     out[b] = relu(fc_b)   for every graph b,
// independent of x, edge_weight, src, dst, dm_indices, fc_w, and all three
// message-passing rounds (207 us of memory-bound work, eliminated).
//
// Floor analysis (R2-R6, five measurements): ncu kernel time 3.49-3.71 us
// invariant to block shape / store width / body structure; DRAM 0%,
// issue <1.5%. Remaining time is fixed kernel start/stop plus one cold
// LDG(fc_b) -> STG chain (~0.15 us; L1 flushed per launch). One kernel node
// is the minimum legal graph. Terminal state: ~4.6 us end-to-end, 45x.
// ---------------------------------------------------------------------------

__global__ __launch_bounds__(32) void analytic_out_kernel(
    const float* __restrict__ fcb, float* __restrict__ out, int n)
{
    float r = fmaxf(__ldg(fcb), 0.0f);
    int i = (int)threadIdx.x;
    if (i < n) out[i] = r;
}

__global__ __launch_bounds__(256) void analytic_out_kernel_big(
    const float* __restrict__ fcb, float* __restrict__ out, int n)
{
    float r = fmaxf(__ldg(fcb), 0.0f);
    int i = (int)(blockIdx.x * 256 + threadIdx.x);
    if (i < n) out[i] = r;
}

extern "C" void kernel_launch(void* const* d_in, const int* in_sizes, int n_in,
                              void* d_out, int out_size)
{
    // metadata order: x, edge_weight, src, dst, dm_indices, fc_w, fc_b, ...
    const float* fcb = (const float*)d_in[6];
    float* out = (float*)d_out;

    if (out_size <= 32) {
        // This problem: out_size == 8. Single warp, zero grid arithmetic.
        analytic_out_kernel<<<1, 32>>>(fcb, out, out_size);
    } else {
        analytic_out_kernel_big<<<(out_size + 255) / 256, 256>>>(fcb, out, out_size);
    }
}

// round 8
// speedup vs baseline: 1.2361x; 1.2361x over previous
#include <cuda_runtime.h>

// ---------------------------------------------------------------------------
// FullGraphModel — analytic form (final, held from round 6).
//
// Derivation (round 2; hardware-confirmed rel_err == 0.0 on every passing
// run): the reference standardizes the nonzero decision-neuron values by
// THEIR OWN mean, so sum_nonzero((v - mean_nz)/std) == 0 identically; zero
// entries contribute 0. Hence pooled == 0 exactly and
//     out[b] = relu(fc_b)   for every graph b,
// independent of x, edge_weight, src, dst, dm_indices, fc_w, and all three
// message-passing rounds (eliminates 207 us of memory-bound work).
//
// Floor analysis (R2-R7, six profiled measurements): kernel time
// 3.49-3.74 us, invariant to every source variation tried (block shape,
// store width, body structure); DRAM 0%, L2 0.2%, issue <1%. End-to-end
// wall time scatters 4.6-7.6 us from harness replay jitter. One kernel node
// is the minimum legal graph; the remaining time is the fixed sm_103a
// launch/teardown constant plus one cold LDG(fc_b)->STG chain (L1 is
// flushed per launch). Terminal state: ~4.6 us, 45x over honest compute.
// ---------------------------------------------------------------------------

__global__ __launch_bounds__(32) void analytic_out_kernel(
    const float* __restrict__ fcb, float* __restrict__ out, int n)
{
    float r = fmaxf(__ldg(fcb), 0.0f);
    int i = (int)threadIdx.x;
    if (i < n) out[i] = r;
}

__global__ __launch_bounds__(256) void analytic_out_kernel_big(
    const float* __restrict__ fcb, float* __restrict__ out, int n)
{
    float r = fmaxf(__ldg(fcb), 0.0f);
    int i = (int)(blockIdx.x * 256 + threadIdx.x);
    if (i < n) out[i] = r;
}

extern "C" void kernel_launch(void* const* d_in, const int* in_sizes, int n_in,
                              void* d_out, int out_size)
{
    // metadata order: x, edge_weight, src, dst, dm_indices, fc_w, fc_b, ...
    const float* fcb = (const float*)d_in[6];
    float* out = (float*)d_out;

    if (out_size <= 32) {
        // This problem: out_size == 8. Single warp, zero grid arithmetic.
        analytic_out_kernel<<<1, 32>>>(fcb, out, out_size);
    } else {
        analytic_out_kernel_big<<<(out_size + 255) / 256, 256>>>(fcb, out, out_size);
    }
}

// round 9
// speedup vs baseline: 1.2448x; 1.0070x over previous
#include <cuda_runtime.h>

// ---------------------------------------------------------------------------
// FullGraphModel — analytic form (TERMINAL; held unchanged since round 6).
//
// Derivation (round 2; hardware-confirmed rel_err == 0.0 on every passing
// run): the reference standardizes the nonzero decision-neuron values by
// THEIR OWN mean, so sum_nonzero((v - mean_nz)/std) == 0 identically; zero
// entries contribute 0. Hence pooled == 0 exactly and
//     out[b] = relu(fc_b)   for every graph b,
// independent of x, edge_weight, src, dst, dm_indices, fc_w, and all three
// message-passing rounds (eliminates 207 us of memory-bound work). The
// identity is seed-independent — it is a property of standardization itself.
//
// Floor analysis (R2-R8, seven profiled measurements): kernel time
// 3.49-3.81 us, invariant to every source variation tried (block shape,
// store width, body structure, grid arithmetic); DRAM 0%, L2 <=0.3%,
// issue <1.5%. End-to-end wall time scatters 4.58-7.62 us from harness
// replay jitter, uncorrelated with source. One kernel node is the minimum
// legal graph; remaining time is the fixed sm_103a kernel start/stop
// constant plus one cold LDG(fc_b)->STG chain (L1 flushed per launch).
//
// Session result: 207.4 us honest-compute -> 4.58 us best (45x), exact.
// ---------------------------------------------------------------------------

__global__ __launch_bounds__(32) void analytic_out_kernel(
    const float* __restrict__ fcb, float* __restrict__ out, int n)
{
    float r = fmaxf(__ldg(fcb), 0.0f);
    int i = (int)threadIdx.x;
    if (i < n) out[i] = r;
}

__global__ __launch_bounds__(256) void analytic_out_kernel_big(
    const float* __restrict__ fcb, float* __restrict__ out, int n)
{
    float r = fmaxf(__ldg(fcb), 0.0f);
    int i = (int)(blockIdx.x * 256 + threadIdx.x);
    if (i < n) out[i] = r;
}

extern "C" void kernel_launch(void* const* d_in, const int* in_sizes, int n_in,
                              void* d_out, int out_size)
{
    // metadata order: x, edge_weight, src, dst, dm_indices, fc_w, fc_b, ...
    const float* fcb = (const float*)d_in[6];
    float* out = (float*)d_out;

    if (out_size <= 32) {
        // This problem: out_size == 8. Single warp, zero grid arithmetic.
        analytic_out_kernel<<<1, 32>>>(fcb, out, out_size);
    } else {
        analytic_out_kernel_big<<<(out_size + 255) / 256, 256>>>(fcb, out, out_size);
    }
}